// round 16
// baseline (speedup 1.0000x reference)
#include <cuda_runtime.h>
#include <cuda_bf16.h>
#include <cuda_fp16.h>
#include <math.h>

#define NN   100000
#define NE   1600000
#define F    128
#define OUTD 32
#define BN_EPS 1e-5f
#define NCHUNK 196   // 196*512 = 100352 >= NN

// ---------------- scratch (device globals; no allocation allowed) ----------------
__device__ int   g_degi[NN];
__device__ float g_inv[NN];
__device__ float g_w[NN];          // w[s] = sum over edges with src==s of inv_deg[dst]
__device__ int   g_off[NN + 1];    // LOCAL exclusive prefix within 512-chunk
__device__ int   g_cur[NN];
__device__ int   g_csr[NE];
__device__ int   g_part[NCHUNK];   // scanned chunk bases (exclusive)
__device__ unsigned g_ctr[4];      // last-block counters: 0=node L0, 1=node L1, 2=colsum, 3=part
__device__ __nv_bfloat16 g_aggb[(size_t)NN * F]; // aggregated bf16 (scaled by inv_deg)
__device__ __nv_bfloat16 g_xb[(size_t)NN * F];   // bf16 features
__device__ unsigned char g_x8[(size_t)NN * F];   // e5m2 features (gather path)
__device__ __nv_bfloat16 g_hb0[(size_t)NN * F];  // bf16 layer outputs
__device__ unsigned char g_h8[(size_t)NN * F];   // e5m2 of BN-applied h0 (gather path)
__device__ __nv_bfloat16 g_hb1[(size_t)NN * F];
__device__ float g_sums0[2 * F];
__device__ float g_sums1[2 * F];
__device__ float g_ab0[2 * F];     // BN affine: [0:F) scale a, [F:2F) shift b
__device__ float g_ab1[2 * F];
__device__ float g_m[2 * F];       // [0:F) sum t(h1), [F:2F) sum w*t(h1)

__device__ __forceinline__ float bflo(unsigned w) { return __uint_as_float(w << 16); }
__device__ __forceinline__ float bfhi(unsigned w) { return __uint_as_float(w & 0xffff0000u); }
__device__ __forceinline__ unsigned bfpack(float a, float b) {
    return (unsigned)__bfloat16_as_ushort(__float2bfloat16(a))
         | ((unsigned)__bfloat16_as_ushort(__float2bfloat16(b)) << 16);
}
// two floats -> packed e5m2 pair (byte0 = lo, byte1 = hi)
__device__ __forceinline__ unsigned short f2e5m2x2(float hi, float lo) {
    unsigned short r;
    asm("cvt.rn.satfinite.e5m2x2.f32 %0, %1, %2;" : "=h"(r) : "f"(hi), "f"(lo));
    return r;
}
// expand fp8 bytes {0,1} / {2,3} of a word into half2 (e5m2 byte -> fp16 via <<8)
__device__ __forceinline__ __half2 e5m2_lo(unsigned v) {
    unsigned r;
    asm("prmt.b32 %0, %1, %2, 0x1404;" : "=r"(r) : "r"(v), "r"(0));
    return *(__half2*)&r;
}
__device__ __forceinline__ __half2 e5m2_hi(unsigned v) {
    unsigned r;
    asm("prmt.b32 %0, %1, %2, 0x3424;" : "=r"(r) : "r"(v), "r"(0));
    return *(__half2*)&r;
}

// ---------------- init ----------------
__global__ void k_zero() {
    int i = blockIdx.x * blockDim.x + threadIdx.x;
    int stride = gridDim.x * blockDim.x;
    for (; i < NN; i += stride) { g_degi[i] = 0; g_cur[i] = 0; g_w[i] = 0.0f; }
    if (blockIdx.x == 0 && threadIdx.x < 2 * F) {
        g_sums0[threadIdx.x] = 0.0f;
        g_sums1[threadIdx.x] = 0.0f;
        g_m[threadIdx.x] = 0.0f;
        if (threadIdx.x < 4) g_ctr[threadIdx.x] = 0u;
    }
}

// ---------------- fused: degree histogram + feat->bf16+e5m2 conversion ----------------
#define HIST_BLOCKS 2048
#define CVT_BLOCKS  1552
__global__ void k_histcvt(const int* __restrict__ dst, const float* __restrict__ feat) {
    if (blockIdx.x < HIST_BLOCKS) {
        int i = blockIdx.x * 256 + threadIdx.x;
        int stride = HIST_BLOCKS * 256;
        for (; i < NE; i += stride) atomicAdd(&g_degi[dst[i]], 1);
    } else {
        size_t i = (size_t)(blockIdx.x - HIST_BLOCKS) * 256 + threadIdx.x;
        size_t stride = (size_t)CVT_BLOCKS * 256;
        size_t n4 = (size_t)NN * F / 4;
        const float4* src4 = (const float4*)feat;
        uint2* db = (uint2*)g_xb;
        unsigned* d8 = (unsigned*)g_x8;
        for (; i < n4; i += stride) {
            float4 v = src4[i];
            db[i] = make_uint2(bfpack(v.x, v.y), bfpack(v.z, v.w));
            unsigned short p0 = f2e5m2x2(v.y, v.x);
            unsigned short p1 = f2e5m2x2(v.w, v.z);
            d8[i] = (unsigned)p0 | ((unsigned)p1 << 16);
        }
    }
}

// ---------------- CSR build: local prefix + inv_deg; last block scans chunk bases ----------------
__global__ void k_part() {
    __shared__ int sh[512];
    __shared__ unsigned lastb;
    int c = blockIdx.x, t = threadIdx.x;
    int i = c * 512 + t;
    int v = (i < NN) ? g_degi[i] : 0;
    if (i < NN) g_inv[i] = 1.0f / fmaxf((float)v, 1.0f);
    sh[t] = v;
    __syncthreads();
    for (int d = 1; d < 512; d <<= 1) {
        int u = (t >= d) ? sh[t - d] : 0;
        __syncthreads();
        sh[t] += u;
        __syncthreads();
    }
    if (i <= NN) g_off[i] = sh[t] - v;      // local exclusive prefix
    if (t == 511) g_part[c] = sh[511];      // chunk total
    __threadfence();
    __syncthreads();
    if (t == 0) lastb = (atomicAdd(&g_ctr[3], 1u) == (unsigned)(gridDim.x - 1));
    __syncthreads();
    if (lastb) {
        __shared__ int sh2[256];
        if (t < 256) sh2[t] = (t < NCHUNK) ? g_part[t] : 0;
        __syncthreads();
        for (int d = 1; d < 256; d <<= 1) {
            int u = (t < 256 && t >= d) ? sh2[t - d] : 0;
            __syncthreads();
            if (t < 256) sh2[t] += u;
            __syncthreads();
        }
        if (t < NCHUNK) g_part[t] = (t == 0) ? 0 : sh2[t - 1];  // exclusive bases
    }
}

// merged CSR fill + src-weight accumulation (one edge pass)
__global__ void k_csrw(const int* __restrict__ src, const int* __restrict__ dst) {
    int i = blockIdx.x * blockDim.x + threadIdx.x;
    int stride = gridDim.x * blockDim.x;
    for (; i < NE; i += stride) {
        int d = dst[i];
        int s = src[i];
        float iv = g_inv[d];
        int p = atomicAdd(&g_cur[d], 1);
        g_csr[g_part[d >> 9] + g_off[d] + p] = s;
        atomicAdd(&g_w[s], iv);
    }
}

// ---------------- CSR aggregation from e5m2: aggb[n] = bf16( inv[n] * sum x8[s] ) ----
__global__ void k_agg(const unsigned char* __restrict__ x8) {
    int lane = threadIdx.x & 31;
    int half = lane >> 4;          // 0/1: edge parity
    int c = lane & 15;             // uint2 index within row (8 features)
    int warp = (blockIdx.x * blockDim.x + threadIdx.x) >> 5;
    int nwarp = (gridDim.x * blockDim.x) >> 5;
    for (int n = warp; n < NN; n += nwarp) {
        int e0 = g_part[n >> 9] + g_off[n];
        int e1 = g_part[(n + 1) >> 9] + g_off[n + 1];
        __half2 hacc[4];
        #pragma unroll
        for (int i = 0; i < 4; i++) hacc[i] = __float2half2_rn(0.f);
        int e = e0 + half;
        for (; e + 2 < e1; e += 4) {
            int s0 = g_csr[e];
            int s1 = g_csr[e + 2];
            uint2 v0 = ((const uint2*)(x8 + (size_t)s0 * F))[c];
            uint2 v1 = ((const uint2*)(x8 + (size_t)s1 * F))[c];
            hacc[0] = __hadd2(hacc[0], __hadd2(e5m2_lo(v0.x), e5m2_lo(v1.x)));
            hacc[1] = __hadd2(hacc[1], __hadd2(e5m2_hi(v0.x), e5m2_hi(v1.x)));
            hacc[2] = __hadd2(hacc[2], __hadd2(e5m2_lo(v0.y), e5m2_lo(v1.y)));
            hacc[3] = __hadd2(hacc[3], __hadd2(e5m2_hi(v0.y), e5m2_hi(v1.y)));
        }
        if (e < e1) {
            int s0 = g_csr[e];
            uint2 v = ((const uint2*)(x8 + (size_t)s0 * F))[c];
            hacc[0] = __hadd2(hacc[0], e5m2_lo(v.x));
            hacc[1] = __hadd2(hacc[1], e5m2_hi(v.x));
            hacc[2] = __hadd2(hacc[2], e5m2_lo(v.y));
            hacc[3] = __hadd2(hacc[3], e5m2_hi(v.y));
        }
        float acc[8];
        #pragma unroll
        for (int i = 0; i < 4; i++) {
            float2 f = __half22float2(hacc[i]);
            acc[i * 2] = f.x; acc[i * 2 + 1] = f.y;
        }
        #pragma unroll
        for (int i = 0; i < 8; i++)
            acc[i] += __shfl_xor_sync(0xffffffffu, acc[i], 16);
        if (half == 0) {
            float w = g_inv[n];
            uint4 o;
            o.x = bfpack(acc[0] * w, acc[1] * w);
            o.y = bfpack(acc[2] * w, acc[3] * w);
            o.z = bfpack(acc[4] * w, acc[5] * w);
            o.w = bfpack(acc[6] * w, acc[7] * w);
            ((uint4*)(g_aggb + (size_t)n * F))[c] = o;
        }
    }
}

// ================= tensor-core node update ==============================
// C[64 x 128] = X[64 x 256] @ W[256 x 128],  X = [x_bf16 | agg_bf16],  W = [Ws; Wn]
// weights split-bf16 (hi+lo); X plain bf16 -> 2 mma per k-step.
// Warp tile 32x32 with 2-way split-K (kk = wid>>3); K-partials reduced through the
// retired A buffer. A tile double-buffered via cp.async. Last block computes BN affine.
#define WW_STRIDE 136
#define SA_STRIDE 132
#define ABUF (64 * SA_STRIDE)
#define OFF_WLO  (128 * WW_STRIDE)
#define OFF_AHI  (2 * 128 * WW_STRIDE)
#define SMEM_WORDS (2 * 128 * WW_STRIDE + 2 * ABUF)
#define SMEM_NODE (SMEM_WORDS * 4)
#define NTILES ((NN + 63) / 64)

__device__ __forceinline__ void cvt_pair(float vx, float vy, unsigned& hi, unsigned& lo) {
    __nv_bfloat16 hx = __float2bfloat16(vx);
    __nv_bfloat16 hy = __float2bfloat16(vy);
    __nv_bfloat16 lx = __float2bfloat16(vx - __bfloat162float(hx));
    __nv_bfloat16 ly = __float2bfloat16(vy - __bfloat162float(hy));
    hi = (unsigned)__bfloat16_as_ushort(hx) | ((unsigned)__bfloat16_as_ushort(hy) << 16);
    lo = (unsigned)__bfloat16_as_ushort(lx) | ((unsigned)__bfloat16_as_ushort(ly) << 16);
}

__device__ __forceinline__ void mma_bf16(float* c, unsigned a0, unsigned a1, unsigned a2,
                                         unsigned a3, unsigned b0, unsigned b1) {
    asm volatile(
        "mma.sync.aligned.m16n8k16.row.col.f32.bf16.bf16.f32 "
        "{%0,%1,%2,%3}, {%4,%5,%6,%7}, {%8,%9}, {%0,%1,%2,%3};"
        : "+f"(c[0]), "+f"(c[1]), "+f"(c[2]), "+f"(c[3])
        : "r"(a0), "r"(a1), "r"(a2), "r"(a3), "r"(b0), "r"(b1));
}

__device__ __forceinline__ void cp_async16(unsigned* dst, const void* src) {
    unsigned daddr = (unsigned)__cvta_generic_to_shared(dst);
    asm volatile("cp.async.cg.shared.global [%0], [%1], 16;" :: "r"(daddr), "l"(src));
}

// stage one 64-node X tile into the given A buffer via cp.async (caller commits)
__device__ __forceinline__ void stage_tile_async(const __nv_bfloat16* __restrict__ x,
                                                 unsigned* __restrict__ abuf,
                                                 int nb, int sr, int cb) {
    int gn = nb + sr;
    unsigned* dhi = abuf + sr * SA_STRIDE + cb * 16;
    if (gn < NN) {
        const uint4* p = (cb < 4)
            ? ((const uint4*)(x + (size_t)gn * F) + cb * 4)
            : ((const uint4*)(g_aggb + (size_t)gn * F) + (cb - 4) * 4);
        #pragma unroll
        for (int i = 0; i < 4; i++) cp_async16(dhi + i * 4, p + i);
    } else {
        #pragma unroll
        for (int i = 0; i < 16; i++) dhi[i] = 0u;
    }
}

__global__ void __launch_bounds__(512, 1)
k_node(const __nv_bfloat16* __restrict__ x,
       const float* __restrict__ Ws,
       const float* __restrict__ Wn,
       const float* __restrict__ bias,
       __nv_bfloat16* __restrict__ out,
       float* __restrict__ sums,        // [2F] BN stats accumulator
       const float* __restrict__ gamma,
       const float* __restrict__ beta,
       float* __restrict__ abp,         // [2F] BN affine output
       int cidx) {                      // counter index
    extern __shared__ unsigned sm[];
    unsigned* wW_hi = sm;
    unsigned* wW_lo = sm + OFF_WLO;
    unsigned* sA = sm + OFF_AHI;       // two buffers of ABUF words

    int tid = threadIdx.x;
    int lane = tid & 31;
    int wid = tid >> 5;            // 0..15
    int kk = wid >> 3;             // 0/1 -> K-half kk*128
    int warpM = (wid >> 2) & 1;    // rows warpM*32
    int warpN = wid & 3;           // cols warpN*32
    int g = lane >> 2;             // 0..7
    int tg = lane & 3;             // 0..3

    // ---- stage W (hi/lo, k-pair packed, nt-permuted within 32-col groups) ----
    for (int idx = tid; idx < 128 * 128; idx += 512) {
        int kp = idx >> 7, n = idx & 127;
        int k0 = kp * 2, k1 = k0 + 1;
        float w0 = (k0 < F) ? Ws[k0 * F + n] : Wn[(k0 - F) * F + n];
        float w1 = (k1 < F) ? Ws[k1 * F + n] : Wn[(k1 - F) * F + n];
        unsigned hi, lo;
        cvt_pair(w0, w1, hi, lo);
        int c = n & 31;
        int pos = kp * WW_STRIDE + (n & ~31) + ((c & 7) << 2) + (c >> 3);
        wW_hi[pos] = hi;
        wW_lo[pos] = lo;
    }

    int sr = tid >> 3;            // staging row 0..63
    int cb = tid & 7;             // 8 col-blocks of 16 words

    float ls[8], ls2[8];
    #pragma unroll
    for (int i = 0; i < 8; i++) { ls[i] = 0.f; ls2[i] = 0.f; }

    float bcol[8];
    #pragma unroll
    for (int nt = 0; nt < 4; nt++) {
        int col = warpN * 32 + nt * 8 + tg * 2;
        bcol[nt * 2 + 0] = bias[col];
        bcol[nt * 2 + 1] = bias[col + 1];
    }

    // prologue: async-stage first tile into buffer 0
    int tile0 = blockIdx.x;
    if (tile0 < NTILES) stage_tile_async(x, sA, tile0 * 64, sr, cb);
    asm volatile("cp.async.commit_group;");
    int buf = 0;

    for (int tile = tile0; tile < NTILES; tile += gridDim.x) {
        asm volatile("cp.async.wait_group 0;");
        __syncthreads();   // current buf staged (and W on first iter); rbuf writes drained

        // async-stage next tile into the other buffer; overlaps with mma below
        int nxt = tile + gridDim.x;
        if (nxt < NTILES) stage_tile_async(x, sA + (buf ^ 1) * ABUF, nxt * 64, sr, cb);
        asm volatile("cp.async.commit_group;");

        const unsigned* sAc = sA + buf * ABUF;
        float c[2][4][4];
        #pragma unroll
        for (int mg = 0; mg < 2; mg++)
            #pragma unroll
            for (int nt = 0; nt < 4; nt++)
                #pragma unroll
                for (int q = 0; q < 4; q++) c[mg][nt][q] = 0.f;

        #pragma unroll
        for (int s = 0; s < 8; s++) {
            int as = kk * 8 + s;
            unsigned a[2][4];
            #pragma unroll
            for (int mg = 0; mg < 2; mg++) {
                int ai = (warpM * 32 + mg * 16 + g) * SA_STRIDE + as * 8 + tg;
                a[mg][0] = sAc[ai];
                a[mg][1] = sAc[ai + 8 * SA_STRIDE];
                a[mg][2] = sAc[ai + 4];
                a[mg][3] = sAc[ai + 8 * SA_STRIDE + 4];
            }
            int bi = (as * 8 + tg) * WW_STRIDE + warpN * 32 + g * 4;
            uint4 b0h = *(const uint4*)(wW_hi + bi);
            uint4 b1h = *(const uint4*)(wW_hi + bi + 4 * WW_STRIDE);
            uint4 b0l = *(const uint4*)(wW_lo + bi);
            uint4 b1l = *(const uint4*)(wW_lo + bi + 4 * WW_STRIDE);
            #pragma unroll
            for (int mg = 0; mg < 2; mg++) {
                mma_bf16(c[mg][0], a[mg][0], a[mg][1], a[mg][2], a[mg][3], b0h.x, b1h.x);
                mma_bf16(c[mg][0], a[mg][0], a[mg][1], a[mg][2], a[mg][3], b0l.x, b1l.x);
                mma_bf16(c[mg][1], a[mg][0], a[mg][1], a[mg][2], a[mg][3], b0h.y, b1h.y);
                mma_bf16(c[mg][1], a[mg][0], a[mg][1], a[mg][2], a[mg][3], b0l.y, b1l.y);
                mma_bf16(c[mg][2], a[mg][0], a[mg][1], a[mg][2], a[mg][3], b0h.z, b1h.z);
                mma_bf16(c[mg][2], a[mg][0], a[mg][1], a[mg][2], a[mg][3], b0l.z, b1l.z);
                mma_bf16(c[mg][3], a[mg][0], a[mg][1], a[mg][2], a[mg][3], b0h.w, b1h.w);
                mma_bf16(c[mg][3], a[mg][0], a[mg][1], a[mg][2], a[mg][3], b0l.w, b1l.w);
            }
        }

        // ---- split-K reduction through retired A buffer + epilogue ----
        __syncthreads();   // all warps finished reading sA[buf]
        float* rbuf = (float*)(sA + buf * ABUF);
        if (kk == 1) {
            #pragma unroll
            for (int mg = 0; mg < 2; mg++)
                #pragma unroll
                for (int nt = 0; nt < 4; nt++) {
                    int r = warpM * 32 + mg * 16 + g;
                    int col = warpN * 32 + nt * 8 + tg * 2;
                    *(float2*)&rbuf[r * SA_STRIDE + col] =
                        make_float2(c[mg][nt][0], c[mg][nt][1]);
                    *(float2*)&rbuf[(r + 8) * SA_STRIDE + col] =
                        make_float2(c[mg][nt][2], c[mg][nt][3]);
                }
        }
        __syncthreads();
        if (kk == 0) {
            int nb = tile * 64;
            #pragma unroll
            for (int mg = 0; mg < 2; mg++)
                #pragma unroll
                for (int nt = 0; nt < 4; nt++) {
                    int r = warpM * 32 + mg * 16 + g;
                    int col = warpN * 32 + nt * 8 + tg * 2;
                    float2 p0 = *(float2*)&rbuf[r * SA_STRIDE + col];
                    float2 p1 = *(float2*)&rbuf[(r + 8) * SA_STRIDE + col];
                    float v0 = fmaxf(c[mg][nt][0] + p0.x + bcol[nt * 2], 0.f);
                    float v1 = fmaxf(c[mg][nt][1] + p0.y + bcol[nt * 2 + 1], 0.f);
                    float v2 = fmaxf(c[mg][nt][2] + p1.x + bcol[nt * 2], 0.f);
                    float v3 = fmaxf(c[mg][nt][3] + p1.y + bcol[nt * 2 + 1], 0.f);
                    int r0 = nb + r;
                    int r1 = nb + r + 8;
                    if (r0 < NN) {
                        unsigned pw = bfpack(v0, v1);
                        *(unsigned*)(out + (size_t)r0 * F + col) = pw;
                        float q0 = bflo(pw), q1 = bfhi(pw);
                        ls[nt * 2] += q0;  ls2[nt * 2] += q0 * q0;
                        ls[nt * 2 + 1] += q1; ls2[nt * 2 + 1] += q1 * q1;
                    }
                    if (r1 < NN) {
                        unsigned pw = bfpack(v2, v3);
                        *(unsigned*)(out + (size_t)r1 * F + col) = pw;
                        float q0 = bflo(pw), q1 = bfhi(pw);
                        ls[nt * 2] += q0;  ls2[nt * 2] += q0 * q0;
                        ls[nt * 2 + 1] += q1; ls2[nt * 2 + 1] += q1 * q1;
                    }
                }
        }
        buf ^= 1;
    }

    // ---- BN stats: smem reduce then one global atomic per column ----
    asm volatile("cp.async.wait_group 0;");
    __syncthreads();
    float* red = (float*)sA;
    for (int i = tid; i < 2 * F; i += 512) red[i] = 0.f;
    __syncthreads();
    #pragma unroll
    for (int nt = 0; nt < 4; nt++) {
        int col = warpN * 32 + nt * 8 + tg * 2;
        atomicAdd(&red[col], ls[nt * 2]);
        atomicAdd(&red[col + 1], ls[nt * 2 + 1]);
        atomicAdd(&red[F + col], ls2[nt * 2]);
        atomicAdd(&red[F + col + 1], ls2[nt * 2 + 1]);
    }
    __syncthreads();
    if (tid < 2 * F) atomicAdd(&sums[tid], red[tid]);

    // ---- last block computes BN affine (fused bnfin) ----
    __threadfence();
    __syncthreads();
    __shared__ unsigned lastb;
    if (tid == 0) lastb = (atomicAdd(&g_ctr[cidx], 1u) == (unsigned)(gridDim.x - 1));
    __syncthreads();
    if (lastb && tid < F) {
        float invN = 1.0f / (float)NN;
        float mu = sums[tid] * invN;
        float var = sums[F + tid] * invN - mu * mu;
        float a = gamma[tid] * rsqrtf(var + BN_EPS);
        abp[tid] = a;
        abp[F + tid] = beta[tid] - mu * a;
    }
}

// ---------------- apply BN affine + relu in place (bf16) + write e5m2 copy ----------------
// fp32 affine math; e5m2 quantization strictly AFTER affine+relu (precision-critical).
__global__ void k_bnapply_b(__nv_bfloat16* __restrict__ h, const float* __restrict__ ab,
                            unsigned char* __restrict__ h8) {
    size_t i = (size_t)blockIdx.x * blockDim.x + threadIdx.x;
    size_t stride = (size_t)gridDim.x * blockDim.x;
    int fp = (int)(i & 31) * 4;    // 32 uint2-words per 128-feature row
    float a0 = ab[fp], a1 = ab[fp + 1], a2 = ab[fp + 2], a3 = ab[fp + 3];
    float b0 = ab[F + fp], b1 = ab[F + fp + 1], b2 = ab[F + fp + 2], b3 = ab[F + fp + 3];
    uint2* hw = (uint2*)h;
    unsigned* h8w = (unsigned*)h8;
    size_t nw = (size_t)NN * (F / 4);
    for (; i < nw; i += stride) {
        uint2 w = hw[i];
        float f0 = fmaxf(fmaf(bflo(w.x), a0, b0), 0.f);
        float f1 = fmaxf(fmaf(bfhi(w.x), a1, b1), 0.f);
        float f2 = fmaxf(fmaf(bflo(w.y), a2, b2), 0.f);
        float f3 = fmaxf(fmaf(bfhi(w.y), a3, b3), 0.f);
        hw[i] = make_uint2(bfpack(f0, f1), bfpack(f2, f3));
        unsigned short p0 = f2e5m2x2(f1, f0);
        unsigned short p1 = f2e5m2x2(f3, f2);
        h8w[i] = (unsigned)p0 | ((unsigned)p1 << 16);
    }
}

// ---------------- final readout + softmax fused ----------------
// BN1 affine + relu fused here (h1 is raw pre-BN output); last block does layer 2 + softmax.
__global__ void k_colsum2(const __nv_bfloat16* __restrict__ h, const float* __restrict__ ab,
                          const float* __restrict__ Ws2, const float* __restrict__ Wn2,
                          const float* __restrict__ b2, float* __restrict__ outp) {
    __shared__ float red[2 * F];
    int tid = threadIdx.x;
    int wd = tid & 63;            // word (feature pair)
    int ro = tid >> 6;            // 0..3 row offset
    float a0 = ab[wd * 2], a1 = ab[wd * 2 + 1];
    float b0 = ab[F + wd * 2], b1 = ab[F + wd * 2 + 1];
    for (int i = tid; i < 2 * F; i += 256) red[i] = 0.f;
    __syncthreads();
    float s0a = 0.f, s0b = 0.f, s1a = 0.f, s1b = 0.f;
    const unsigned* hw = (const unsigned*)h;
    for (int n = blockIdx.x * 4 + ro; n < NN; n += gridDim.x * 4) {
        unsigned v = hw[(size_t)n * 64 + wd];
        float f0 = fmaxf(fmaf(bflo(v), a0, b0), 0.f);
        float f1 = fmaxf(fmaf(bfhi(v), a1, b1), 0.f);
        float w = g_w[n];
        s0a += f0; s0b += f1;
        s1a += w * f0; s1b += w * f1;
    }
    atomicAdd(&red[wd * 2], s0a);
    atomicAdd(&red[wd * 2 + 1], s0b);
    atomicAdd(&red[F + wd * 2], s1a);
    atomicAdd(&red[F + wd * 2 + 1], s1b);
    __syncthreads();
    if (tid < 2 * F) atomicAdd(&g_m[tid], red[tid]);

    // ---- last block: layer-2 GEMV + softmax (fused k_final) ----
    __threadfence();
    __syncthreads();
    __shared__ unsigned lastb;
    if (tid == 0) lastb = (atomicAdd(&g_ctr[2], 1u) == (unsigned)(gridDim.x - 1));
    __syncthreads();
    if (lastb && tid < 32) {
        int o = tid;
        float invN = 1.0f / (float)NN;
        float acc = b2[o];
        #pragma unroll 4
        for (int k = 0; k < F; k++) {
            acc = fmaf(g_m[k] * invN, Ws2[k * OUTD + o], acc);
            acc = fmaf(g_m[F + k] * invN, Wn2[k * OUTD + o], acc);
        }
        float m = acc;
        #pragma unroll
        for (int off = 16; off; off >>= 1)
            m = fmaxf(m, __shfl_xor_sync(0xffffffffu, m, off));
        float e = expf(acc - m);
        float s = e;
        #pragma unroll
        for (int off = 16; off; off >>= 1)
            s += __shfl_xor_sync(0xffffffffu, s, off);
        outp[o] = e / s;
    }
}

// ---------------- launch ----------------
extern "C" void kernel_launch(void* const* d_in, const int* in_sizes, int n_in,
                              void* d_out, int out_size) {
    const float* feat = (const float*)d_in[0];
    const int*   src  = (const int*)d_in[1];
    const int*   dst  = (const int*)d_in[2];
    const float* Ws0  = (const float*)d_in[3];
    const float* Wn0  = (const float*)d_in[4];
    const float* b0   = (const float*)d_in[5];
    const float* Ws1  = (const float*)d_in[6];
    const float* Wn1  = (const float*)d_in[7];
    const float* b1   = (const float*)d_in[8];
    const float* Ws2  = (const float*)d_in[9];
    const float* Wn2  = (const float*)d_in[10];
    const float* b2   = (const float*)d_in[11];
    const float* g0   = (const float*)d_in[12];
    const float* be0  = (const float*)d_in[13];
    const float* g1   = (const float*)d_in[14];
    const float* be1  = (const float*)d_in[15];
    float* out = (float*)d_out;

    cudaFuncSetAttribute(k_node, cudaFuncAttributeMaxDynamicSharedMemorySize, SMEM_NODE);

    float *s0p, *s1p, *ab0, *ab1;
    __nv_bfloat16 *xb, *hb0, *hb1;
    unsigned char *x8, *h8;
    cudaGetSymbolAddress((void**)&xb, g_xb);
    cudaGetSymbolAddress((void**)&x8, g_x8);
    cudaGetSymbolAddress((void**)&h8, g_h8);
    cudaGetSymbolAddress((void**)&hb0, g_hb0);
    cudaGetSymbolAddress((void**)&hb1, g_hb1);
    cudaGetSymbolAddress((void**)&s0p, g_sums0);
    cudaGetSymbolAddress((void**)&s1p, g_sums1);
    cudaGetSymbolAddress((void**)&ab0, g_ab0);
    cudaGetSymbolAddress((void**)&ab1, g_ab1);

    // init + graph preprocessing
    k_zero<<<196, 512>>>();
    k_histcvt<<<HIST_BLOCKS + CVT_BLOCKS, 256>>>(dst, feat);
    k_part<<<NCHUNK, 512>>>();
    k_csrw<<<2048, 256>>>(src, dst);

    // ---- layer 0 ----
    k_agg<<<12500, 256>>>(x8);
    k_node<<<148, 512, SMEM_NODE>>>(xb, Ws0, Wn0, b0, hb0, s0p, g0, be0, ab0, 0);
    k_bnapply_b<<<1024, 256>>>(hb0, ab0, h8);

    // ---- layer 1 ----
    k_agg<<<12500, 256>>>(h8);
    k_node<<<148, 512, SMEM_NODE>>>(hb0, Ws1, Wn1, b1, hb1, s1p, g1, be1, ab1, 1);

    // ---- layer 2 folded into readout (BN1 + final GEMV + softmax fused) ----
    k_colsum2<<<512, 256>>>(hb1, ab1, Ws2, Wn2, b2, out);
}

// round 17
// speedup vs baseline: 1.0395x; 1.0395x over previous
#include <cuda_runtime.h>
#include <cuda_bf16.h>
#include <cuda_fp16.h>
#include <math.h>

#define NN   100000
#define NE   1600000
#define F    128
#define OUTD 32
#define BN_EPS 1e-5f
#define NCHUNK 196   // 196*512 = 100352 >= NN

// ---------------- scratch (device globals; no allocation allowed) ----------------
__device__ int   g_degi[NN];
__device__ float g_inv[NN];
__device__ float g_w[NN];          // w[s] = sum over edges with src==s of inv_deg[dst]
__device__ int   g_off[NN + 1];    // LOCAL exclusive prefix within 512-chunk
__device__ int   g_cur[NN];
__device__ int   g_csr[NE];
__device__ int   g_part[NCHUNK];   // scanned chunk bases (exclusive)
__device__ unsigned g_ctr[4];      // last-block counters: 0=node L0, 1=node L1, 2=colsum, 3=part
__device__ __nv_bfloat16 g_aggb[(size_t)NN * F]; // aggregated bf16 (scaled by inv_deg)
__device__ __nv_bfloat16 g_xb[(size_t)NN * F];   // bf16 features
__device__ unsigned char g_x8[(size_t)NN * F];   // e5m2 features (gather path)
__device__ __nv_bfloat16 g_hb0[(size_t)NN * F];  // bf16 layer outputs
__device__ unsigned char g_h8[(size_t)NN * F];   // e5m2 of BN-applied h0 (gather path)
__device__ __nv_bfloat16 g_hb1[(size_t)NN * F];
__device__ float g_sums0[2 * F];
__device__ float g_sums1[2 * F];
__device__ float g_ab0[2 * F];     // BN affine: [0:F) scale a, [F:2F) shift b
__device__ float g_ab1[2 * F];
__device__ float g_m[2 * F];       // [0:F) sum t(h1), [F:2F) sum w*t(h1)

__device__ __forceinline__ float bflo(unsigned w) { return __uint_as_float(w << 16); }
__device__ __forceinline__ float bfhi(unsigned w) { return __uint_as_float(w & 0xffff0000u); }
__device__ __forceinline__ unsigned bfpack(float a, float b) {
    return (unsigned)__bfloat16_as_ushort(__float2bfloat16(a))
         | ((unsigned)__bfloat16_as_ushort(__float2bfloat16(b)) << 16);
}
// two floats -> packed e5m2 pair (byte0 = lo, byte1 = hi)
__device__ __forceinline__ unsigned short f2e5m2x2(float hi, float lo) {
    unsigned short r;
    asm("cvt.rn.satfinite.e5m2x2.f32 %0, %1, %2;" : "=h"(r) : "f"(hi), "f"(lo));
    return r;
}
// expand fp8 bytes {0,1} / {2,3} of a word into half2 (e5m2 byte -> fp16 via <<8)
__device__ __forceinline__ __half2 e5m2_lo(unsigned v) {
    unsigned r;
    asm("prmt.b32 %0, %1, %2, 0x1404;" : "=r"(r) : "r"(v), "r"(0));
    return *(__half2*)&r;
}
__device__ __forceinline__ __half2 e5m2_hi(unsigned v) {
    unsigned r;
    asm("prmt.b32 %0, %1, %2, 0x3424;" : "=r"(r) : "r"(v), "r"(0));
    return *(__half2*)&r;
}

// ---------------- init ----------------
__global__ void k_zero() {
    int i = blockIdx.x * blockDim.x + threadIdx.x;
    int stride = gridDim.x * blockDim.x;
    for (; i < NN; i += stride) { g_degi[i] = 0; g_cur[i] = 0; g_w[i] = 0.0f; }
    if (blockIdx.x == 0 && threadIdx.x < 2 * F) {
        g_sums0[threadIdx.x] = 0.0f;
        g_sums1[threadIdx.x] = 0.0f;
        g_m[threadIdx.x] = 0.0f;
        if (threadIdx.x < 4) g_ctr[threadIdx.x] = 0u;
    }
}

// ---------------- fused: degree histogram + feat->bf16+e5m2 conversion ----------------
#define HIST_BLOCKS 2048
#define CVT_BLOCKS  1552
__global__ void k_histcvt(const int* __restrict__ dst, const float* __restrict__ feat) {
    if (blockIdx.x < HIST_BLOCKS) {
        int i = blockIdx.x * 256 + threadIdx.x;
        int stride = HIST_BLOCKS * 256;
        for (; i < NE; i += stride) atomicAdd(&g_degi[dst[i]], 1);
    } else {
        size_t i = (size_t)(blockIdx.x - HIST_BLOCKS) * 256 + threadIdx.x;
        size_t stride = (size_t)CVT_BLOCKS * 256;
        size_t n4 = (size_t)NN * F / 4;
        const float4* src4 = (const float4*)feat;
        uint2* db = (uint2*)g_xb;
        unsigned* d8 = (unsigned*)g_x8;
        for (; i < n4; i += stride) {
            float4 v = src4[i];
            db[i] = make_uint2(bfpack(v.x, v.y), bfpack(v.z, v.w));
            unsigned short p0 = f2e5m2x2(v.y, v.x);
            unsigned short p1 = f2e5m2x2(v.w, v.z);
            d8[i] = (unsigned)p0 | ((unsigned)p1 << 16);
        }
    }
}

// ---------------- CSR build: local prefix + inv_deg; last block scans chunk bases ----------------
__global__ void k_part() {
    __shared__ int sh[512];
    __shared__ unsigned lastb;
    int c = blockIdx.x, t = threadIdx.x;
    int i = c * 512 + t;
    int v = (i < NN) ? g_degi[i] : 0;
    if (i < NN) g_inv[i] = 1.0f / fmaxf((float)v, 1.0f);
    sh[t] = v;
    __syncthreads();
    for (int d = 1; d < 512; d <<= 1) {
        int u = (t >= d) ? sh[t - d] : 0;
        __syncthreads();
        sh[t] += u;
        __syncthreads();
    }
    if (i <= NN) g_off[i] = sh[t] - v;      // local exclusive prefix
    if (t == 511) g_part[c] = sh[511];      // chunk total
    __threadfence();
    __syncthreads();
    if (t == 0) lastb = (atomicAdd(&g_ctr[3], 1u) == (unsigned)(gridDim.x - 1));
    __syncthreads();
    if (lastb) {
        __shared__ int sh2[256];
        if (t < 256) sh2[t] = (t < NCHUNK) ? g_part[t] : 0;
        __syncthreads();
        for (int d = 1; d < 256; d <<= 1) {
            int u = (t < 256 && t >= d) ? sh2[t - d] : 0;
            __syncthreads();
            if (t < 256) sh2[t] += u;
            __syncthreads();
        }
        if (t < NCHUNK) g_part[t] = (t == 0) ? 0 : sh2[t - 1];  // exclusive bases
    }
}

// merged CSR fill + src-weight accumulation; 2-edge batching for atomic MLP
__global__ void k_csrw(const int* __restrict__ src, const int* __restrict__ dst) {
    int i = blockIdx.x * blockDim.x + threadIdx.x;
    int stride = gridDim.x * blockDim.x;
    for (; i + stride < NE; i += 2 * stride) {
        int d0 = dst[i],          s0 = src[i];
        int d1 = dst[i + stride], s1 = src[i + stride];
        float iv0 = g_inv[d0];
        float iv1 = g_inv[d1];
        int p0 = atomicAdd(&g_cur[d0], 1);
        int p1 = atomicAdd(&g_cur[d1], 1);
        g_csr[g_part[d0 >> 9] + g_off[d0] + p0] = s0;
        g_csr[g_part[d1 >> 9] + g_off[d1] + p1] = s1;
        atomicAdd(&g_w[s0], iv0);
        atomicAdd(&g_w[s1], iv1);
    }
    for (; i < NE; i += stride) {
        int d = dst[i];
        int s = src[i];
        float iv = g_inv[d];
        int p = atomicAdd(&g_cur[d], 1);
        g_csr[g_part[d >> 9] + g_off[d] + p] = s;
        atomicAdd(&g_w[s], iv);
    }
}

// ---------------- CSR aggregation from e5m2: aggb[n] = bf16( inv[n] * sum x8[s] ) ----
__global__ void k_agg(const unsigned char* __restrict__ x8) {
    int lane = threadIdx.x & 31;
    int half = lane >> 4;          // 0/1: edge parity
    int c = lane & 15;             // uint2 index within row (8 features)
    int warp = (blockIdx.x * blockDim.x + threadIdx.x) >> 5;
    int nwarp = (gridDim.x * blockDim.x) >> 5;
    for (int n = warp; n < NN; n += nwarp) {
        int e0 = g_part[n >> 9] + g_off[n];
        int e1 = g_part[(n + 1) >> 9] + g_off[n + 1];
        __half2 hacc[4];
        #pragma unroll
        for (int i = 0; i < 4; i++) hacc[i] = __float2half2_rn(0.f);
        int e = e0 + half;
        for (; e + 2 < e1; e += 4) {
            int s0 = g_csr[e];
            int s1 = g_csr[e + 2];
            uint2 v0 = ((const uint2*)(x8 + (size_t)s0 * F))[c];
            uint2 v1 = ((const uint2*)(x8 + (size_t)s1 * F))[c];
            hacc[0] = __hadd2(hacc[0], __hadd2(e5m2_lo(v0.x), e5m2_lo(v1.x)));
            hacc[1] = __hadd2(hacc[1], __hadd2(e5m2_hi(v0.x), e5m2_hi(v1.x)));
            hacc[2] = __hadd2(hacc[2], __hadd2(e5m2_lo(v0.y), e5m2_lo(v1.y)));
            hacc[3] = __hadd2(hacc[3], __hadd2(e5m2_hi(v0.y), e5m2_hi(v1.y)));
        }
        if (e < e1) {
            int s0 = g_csr[e];
            uint2 v = ((const uint2*)(x8 + (size_t)s0 * F))[c];
            hacc[0] = __hadd2(hacc[0], e5m2_lo(v.x));
            hacc[1] = __hadd2(hacc[1], e5m2_hi(v.x));
            hacc[2] = __hadd2(hacc[2], e5m2_lo(v.y));
            hacc[3] = __hadd2(hacc[3], e5m2_hi(v.y));
        }
        float acc[8];
        #pragma unroll
        for (int i = 0; i < 4; i++) {
            float2 f = __half22float2(hacc[i]);
            acc[i * 2] = f.x; acc[i * 2 + 1] = f.y;
        }
        #pragma unroll
        for (int i = 0; i < 8; i++)
            acc[i] += __shfl_xor_sync(0xffffffffu, acc[i], 16);
        if (half == 0) {
            float w = g_inv[n];
            uint4 o;
            o.x = bfpack(acc[0] * w, acc[1] * w);
            o.y = bfpack(acc[2] * w, acc[3] * w);
            o.z = bfpack(acc[4] * w, acc[5] * w);
            o.w = bfpack(acc[6] * w, acc[7] * w);
            ((uint4*)(g_aggb + (size_t)n * F))[c] = o;
        }
    }
}

// ================= tensor-core node update (R14-proven 16x32 warp tile) =========
// C[64 x 128] = X[64 x 256] @ W[256 x 128],  X = [x_bf16 | agg_bf16],  W = [Ws; Wn]
// weights split-bf16 (hi+lo); X plain bf16 -> 2 mma per k-step.
// A tile double-buffered via cp.async. Last finishing block computes BN affine.
#define WW_STRIDE 136
#define SA_STRIDE 132
#define ABUF (64 * SA_STRIDE)
#define OFF_WLO  (128 * WW_STRIDE)
#define OFF_AHI  (2 * 128 * WW_STRIDE)
#define SMEM_WORDS (2 * 128 * WW_STRIDE + 2 * ABUF)
#define SMEM_NODE (SMEM_WORDS * 4)
#define NTILES ((NN + 63) / 64)

__device__ __forceinline__ void cvt_pair(float vx, float vy, unsigned& hi, unsigned& lo) {
    __nv_bfloat16 hx = __float2bfloat16(vx);
    __nv_bfloat16 hy = __float2bfloat16(vy);
    __nv_bfloat16 lx = __float2bfloat16(vx - __bfloat162float(hx));
    __nv_bfloat16 ly = __float2bfloat16(vy - __bfloat162float(hy));
    hi = (unsigned)__bfloat16_as_ushort(hx) | ((unsigned)__bfloat16_as_ushort(hy) << 16);
    lo = (unsigned)__bfloat16_as_ushort(lx) | ((unsigned)__bfloat16_as_ushort(ly) << 16);
}

__device__ __forceinline__ void mma_bf16(float* c, unsigned a0, unsigned a1, unsigned a2,
                                         unsigned a3, unsigned b0, unsigned b1) {
    asm volatile(
        "mma.sync.aligned.m16n8k16.row.col.f32.bf16.bf16.f32 "
        "{%0,%1,%2,%3}, {%4,%5,%6,%7}, {%8,%9}, {%0,%1,%2,%3};"
        : "+f"(c[0]), "+f"(c[1]), "+f"(c[2]), "+f"(c[3])
        : "r"(a0), "r"(a1), "r"(a2), "r"(a3), "r"(b0), "r"(b1));
}

__device__ __forceinline__ void cp_async16(unsigned* dst, const void* src) {
    unsigned daddr = (unsigned)__cvta_generic_to_shared(dst);
    asm volatile("cp.async.cg.shared.global [%0], [%1], 16;" :: "r"(daddr), "l"(src));
}

// stage one 64-node X tile into the given A buffer via cp.async (caller commits)
__device__ __forceinline__ void stage_tile_async(const __nv_bfloat16* __restrict__ x,
                                                 unsigned* __restrict__ abuf,
                                                 int nb, int sr, int cb) {
    int gn = nb + sr;
    unsigned* dhi = abuf + sr * SA_STRIDE + cb * 16;
    if (gn < NN) {
        const uint4* p = (cb < 4)
            ? ((const uint4*)(x + (size_t)gn * F) + cb * 4)
            : ((const uint4*)(g_aggb + (size_t)gn * F) + (cb - 4) * 4);
        #pragma unroll
        for (int i = 0; i < 4; i++) cp_async16(dhi + i * 4, p + i);
    } else {
        #pragma unroll
        for (int i = 0; i < 16; i++) dhi[i] = 0u;
    }
}

__global__ void __launch_bounds__(512, 1)
k_node(const __nv_bfloat16* __restrict__ x,
       const float* __restrict__ Ws,
       const float* __restrict__ Wn,
       const float* __restrict__ bias,
       __nv_bfloat16* __restrict__ out,
       float* __restrict__ sums,        // [2F] BN stats accumulator
       const float* __restrict__ gamma,
       const float* __restrict__ beta,
       float* __restrict__ abp,         // [2F] BN affine output
       int cidx) {                      // counter index
    extern __shared__ unsigned sm[];
    unsigned* wW_hi = sm;
    unsigned* wW_lo = sm + OFF_WLO;
    unsigned* sA = sm + OFF_AHI;       // two buffers of ABUF words

    int tid = threadIdx.x;
    int lane = tid & 31;
    int wid = tid >> 5;            // 0..15
    int warpM = wid >> 2;          // 0..3 -> rows warpM*16
    int warpN = wid & 3;           // 0..3 -> cols warpN*32
    int g = lane >> 2;             // 0..7
    int tg = lane & 3;             // 0..3

    // ---- stage W (hi/lo, k-pair packed, nt-permuted within 32-col groups) ----
    for (int idx = tid; idx < 128 * 128; idx += 512) {
        int kp = idx >> 7, n = idx & 127;
        int k0 = kp * 2, k1 = k0 + 1;
        float w0 = (k0 < F) ? Ws[k0 * F + n] : Wn[(k0 - F) * F + n];
        float w1 = (k1 < F) ? Ws[k1 * F + n] : Wn[(k1 - F) * F + n];
        unsigned hi, lo;
        cvt_pair(w0, w1, hi, lo);
        int c = n & 31;
        int pos = kp * WW_STRIDE + (n & ~31) + ((c & 7) << 2) + (c >> 3);
        wW_hi[pos] = hi;
        wW_lo[pos] = lo;
    }

    int sr = tid >> 3;            // staging row 0..63
    int cb = tid & 7;             // 8 col-blocks of 16 words

    float ls[8], ls2[8];
    #pragma unroll
    for (int i = 0; i < 8; i++) { ls[i] = 0.f; ls2[i] = 0.f; }

    float bcol[8];
    #pragma unroll
    for (int nt = 0; nt < 4; nt++) {
        int col = warpN * 32 + nt * 8 + tg * 2;
        bcol[nt * 2 + 0] = bias[col];
        bcol[nt * 2 + 1] = bias[col + 1];
    }

    // prologue: async-stage first tile into buffer 0
    int tile0 = blockIdx.x;
    if (tile0 < NTILES) stage_tile_async(x, sA, tile0 * 64, sr, cb);
    asm volatile("cp.async.commit_group;");
    int buf = 0;

    for (int tile = tile0; tile < NTILES; tile += gridDim.x) {
        asm volatile("cp.async.wait_group 0;");
        __syncthreads();   // current buf staged (and W on first iter)

        // async-stage next tile into the other buffer; overlaps with mma below
        int nxt = tile + gridDim.x;
        if (nxt < NTILES) stage_tile_async(x, sA + (buf ^ 1) * ABUF, nxt * 64, sr, cb);
        asm volatile("cp.async.commit_group;");

        const unsigned* sAc = sA + buf * ABUF;
        float c[4][4];
        #pragma unroll
        for (int nt = 0; nt < 4; nt++)
            #pragma unroll
            for (int q = 0; q < 4; q++) c[nt][q] = 0.f;

        int rbase = (warpM * 16 + g) * SA_STRIDE;

        #pragma unroll
        for (int s = 0; s < 16; s++) {
            int ai = rbase + s * 8 + tg;
            unsigned a0h = sAc[ai];
            unsigned a1h = sAc[ai + 8 * SA_STRIDE];
            unsigned a2h = sAc[ai + 4];
            unsigned a3h = sAc[ai + 8 * SA_STRIDE + 4];
            int bi = (s * 8 + tg) * WW_STRIDE + warpN * 32 + g * 4;
            uint4 b0h = *(const uint4*)(wW_hi + bi);
            uint4 b1h = *(const uint4*)(wW_hi + bi + 4 * WW_STRIDE);
            uint4 b0l = *(const uint4*)(wW_lo + bi);
            uint4 b1l = *(const uint4*)(wW_lo + bi + 4 * WW_STRIDE);
            mma_bf16(c[0], a0h, a1h, a2h, a3h, b0h.x, b1h.x);
            mma_bf16(c[0], a0h, a1h, a2h, a3h, b0l.x, b1l.x);
            mma_bf16(c[1], a0h, a1h, a2h, a3h, b0h.y, b1h.y);
            mma_bf16(c[1], a0h, a1h, a2h, a3h, b0l.y, b1l.y);
            mma_bf16(c[2], a0h, a1h, a2h, a3h, b0h.z, b1h.z);
            mma_bf16(c[2], a0h, a1h, a2h, a3h, b0l.z, b1l.z);
            mma_bf16(c[3], a0h, a1h, a2h, a3h, b0h.w, b1h.w);
            mma_bf16(c[3], a0h, a1h, a2h, a3h, b0l.w, b1l.w);
        }

        // ---- epilogue: bias + relu + bf16 store + BN stats (on rounded values) ----
        int nb = tile * 64;
        int r0 = nb + warpM * 16 + g;
        int r1 = r0 + 8;
        #pragma unroll
        for (int nt = 0; nt < 4; nt++) {
            int col = warpN * 32 + nt * 8 + tg * 2;
            float v0 = fmaxf(c[nt][0] + bcol[nt * 2], 0.f);
            float v1 = fmaxf(c[nt][1] + bcol[nt * 2 + 1], 0.f);
            float v2 = fmaxf(c[nt][2] + bcol[nt * 2], 0.f);
            float v3 = fmaxf(c[nt][3] + bcol[nt * 2 + 1], 0.f);
            if (r0 < NN) {
                unsigned pw = bfpack(v0, v1);
                *(unsigned*)(out + (size_t)r0 * F + col) = pw;
                float q0 = bflo(pw), q1 = bfhi(pw);
                ls[nt * 2] += q0;  ls2[nt * 2] += q0 * q0;
                ls[nt * 2 + 1] += q1; ls2[nt * 2 + 1] += q1 * q1;
            }
            if (r1 < NN) {
                unsigned pw = bfpack(v2, v3);
                *(unsigned*)(out + (size_t)r1 * F + col) = pw;
                float q0 = bflo(pw), q1 = bfhi(pw);
                ls[nt * 2] += q0;  ls2[nt * 2] += q0 * q0;
                ls[nt * 2 + 1] += q1; ls2[nt * 2 + 1] += q1 * q1;
            }
        }
        buf ^= 1;
    }

    // ---- BN stats: smem reduce then one global atomic per column ----
    asm volatile("cp.async.wait_group 0;");
    __syncthreads();
    float* red = (float*)sA;
    for (int i = tid; i < 2 * F; i += 512) red[i] = 0.f;
    __syncthreads();
    #pragma unroll
    for (int nt = 0; nt < 4; nt++) {
        int col = warpN * 32 + nt * 8 + tg * 2;
        atomicAdd(&red[col], ls[nt * 2]);
        atomicAdd(&red[col + 1], ls[nt * 2 + 1]);
        atomicAdd(&red[F + col], ls2[nt * 2]);
        atomicAdd(&red[F + col + 1], ls2[nt * 2 + 1]);
    }
    __syncthreads();
    if (tid < 2 * F) atomicAdd(&sums[tid], red[tid]);

    // ---- last block computes BN affine (fused bnfin) ----
    __threadfence();
    __syncthreads();
    __shared__ unsigned lastb;
    if (tid == 0) lastb = (atomicAdd(&g_ctr[cidx], 1u) == (unsigned)(gridDim.x - 1));
    __syncthreads();
    if (lastb && tid < F) {
        float invN = 1.0f / (float)NN;
        float mu = sums[tid] * invN;
        float var = sums[F + tid] * invN - mu * mu;
        float a = gamma[tid] * rsqrtf(var + BN_EPS);
        abp[tid] = a;
        abp[F + tid] = beta[tid] - mu * a;
    }
}

// ---------------- apply BN affine + relu in place (bf16) + write e5m2 copy ----------------
// fp32 affine math; e5m2 quantization strictly AFTER affine+relu (precision-critical).
__global__ void k_bnapply_b(__nv_bfloat16* __restrict__ h, const float* __restrict__ ab,
                            unsigned char* __restrict__ h8) {
    size_t i = (size_t)blockIdx.x * blockDim.x + threadIdx.x;
    size_t stride = (size_t)gridDim.x * blockDim.x;
    int fp = (int)(i & 31) * 4;    // 32 uint2-words per 128-feature row
    float a0 = ab[fp], a1 = ab[fp + 1], a2 = ab[fp + 2], a3 = ab[fp + 3];
    float b0 = ab[F + fp], b1 = ab[F + fp + 1], b2 = ab[F + fp + 2], b3 = ab[F + fp + 3];
    uint2* hw = (uint2*)h;
    unsigned* h8w = (unsigned*)h8;
    size_t nw = (size_t)NN * (F / 4);
    for (; i < nw; i += stride) {
        uint2 w = hw[i];
        float f0 = fmaxf(fmaf(bflo(w.x), a0, b0), 0.f);
        float f1 = fmaxf(fmaf(bfhi(w.x), a1, b1), 0.f);
        float f2 = fmaxf(fmaf(bflo(w.y), a2, b2), 0.f);
        float f3 = fmaxf(fmaf(bfhi(w.y), a3, b3), 0.f);
        hw[i] = make_uint2(bfpack(f0, f1), bfpack(f2, f3));
        unsigned short p0 = f2e5m2x2(f1, f0);
        unsigned short p1 = f2e5m2x2(f3, f2);
        h8w[i] = (unsigned)p0 | ((unsigned)p1 << 16);
    }
}

// ---------------- final readout + softmax fused ----------------
// BN1 affine + relu fused here (h1 is raw pre-BN output); last block does layer 2 + softmax.
__global__ void k_colsum2(const __nv_bfloat16* __restrict__ h, const float* __restrict__ ab,
                          const float* __restrict__ Ws2, const float* __restrict__ Wn2,
                          const float* __restrict__ b2, float* __restrict__ outp) {
    __shared__ float red[2 * F];
    int tid = threadIdx.x;
    int wd = tid & 63;            // word (feature pair)
    int ro = tid >> 6;            // 0..3 row offset
    float a0 = ab[wd * 2], a1 = ab[wd * 2 + 1];
    float b0 = ab[F + wd * 2], b1 = ab[F + wd * 2 + 1];
    for (int i = tid; i < 2 * F; i += 256) red[i] = 0.f;
    __syncthreads();
    float s0a = 0.f, s0b = 0.f, s1a = 0.f, s1b = 0.f;
    const unsigned* hw = (const unsigned*)h;
    for (int n = blockIdx.x * 4 + ro; n < NN; n += gridDim.x * 4) {
        unsigned v = hw[(size_t)n * 64 + wd];
        float f0 = fmaxf(fmaf(bflo(v), a0, b0), 0.f);
        float f1 = fmaxf(fmaf(bfhi(v), a1, b1), 0.f);
        float w = g_w[n];
        s0a += f0; s0b += f1;
        s1a += w * f0; s1b += w * f1;
    }
    atomicAdd(&red[wd * 2], s0a);
    atomicAdd(&red[wd * 2 + 1], s0b);
    atomicAdd(&red[F + wd * 2], s1a);
    atomicAdd(&red[F + wd * 2 + 1], s1b);
    __syncthreads();
    if (tid < 2 * F) atomicAdd(&g_m[tid], red[tid]);

    // ---- last block: layer-2 GEMV + softmax (fused k_final) ----
    __threadfence();
    __syncthreads();
    __shared__ unsigned lastb;
    if (tid == 0) lastb = (atomicAdd(&g_ctr[2], 1u) == (unsigned)(gridDim.x - 1));
    __syncthreads();
    if (lastb && tid < 32) {
        int o = tid;
        float invN = 1.0f / (float)NN;
        float acc = b2[o];
        #pragma unroll 4
        for (int k = 0; k < F; k++) {
            acc = fmaf(g_m[k] * invN, Ws2[k * OUTD + o], acc);
            acc = fmaf(g_m[F + k] * invN, Wn2[k * OUTD + o], acc);
        }
        float m = acc;
        #pragma unroll
        for (int off = 16; off; off >>= 1)
            m = fmaxf(m, __shfl_xor_sync(0xffffffffu, m, off));
        float e = expf(acc - m);
        float s = e;
        #pragma unroll
        for (int off = 16; off; off >>= 1)
            s += __shfl_xor_sync(0xffffffffu, s, off);
        outp[o] = e / s;
    }
}

// ---------------- launch ----------------
extern "C" void kernel_launch(void* const* d_in, const int* in_sizes, int n_in,
                              void* d_out, int out_size) {
    const float* feat = (const float*)d_in[0];
    const int*   src  = (const int*)d_in[1];
    const int*   dst  = (const int*)d_in[2];
    const float* Ws0  = (const float*)d_in[3];
    const float* Wn0  = (const float*)d_in[4];
    const float* b0   = (const float*)d_in[5];
    const float* Ws1  = (const float*)d_in[6];
    const float* Wn1  = (const float*)d_in[7];
    const float* b1   = (const float*)d_in[8];
    const float* Ws2  = (const float*)d_in[9];
    const float* Wn2  = (const float*)d_in[10];
    const float* b2   = (const float*)d_in[11];
    const float* g0   = (const float*)d_in[12];
    const float* be0  = (const float*)d_in[13];
    const float* g1   = (const float*)d_in[14];
    const float* be1  = (const float*)d_in[15];
    float* out = (float*)d_out;

    cudaFuncSetAttribute(k_node, cudaFuncAttributeMaxDynamicSharedMemorySize, SMEM_NODE);

    float *s0p, *s1p, *ab0, *ab1;
    __nv_bfloat16 *xb, *hb0, *hb1;
    unsigned char *x8, *h8;
    cudaGetSymbolAddress((void**)&xb, g_xb);
    cudaGetSymbolAddress((void**)&x8, g_x8);
    cudaGetSymbolAddress((void**)&h8, g_h8);
    cudaGetSymbolAddress((void**)&hb0, g_hb0);
    cudaGetSymbolAddress((void**)&hb1, g_hb1);
    cudaGetSymbolAddress((void**)&s0p, g_sums0);
    cudaGetSymbolAddress((void**)&s1p, g_sums1);
    cudaGetSymbolAddress((void**)&ab0, g_ab0);
    cudaGetSymbolAddress((void**)&ab1, g_ab1);

    // init + graph preprocessing
    k_zero<<<196, 512>>>();
    k_histcvt<<<HIST_BLOCKS + CVT_BLOCKS, 256>>>(dst, feat);
    k_part<<<NCHUNK, 512>>>();
    k_csrw<<<2048, 256>>>(src, dst);

    // ---- layer 0 ----
    k_agg<<<12500, 256>>>(x8);
    k_node<<<148, 512, SMEM_NODE>>>(xb, Ws0, Wn0, b0, hb0, s0p, g0, be0, ab0, 0);
    k_bnapply_b<<<1024, 256>>>(hb0, ab0, h8);

    // ---- layer 1 ----
    k_agg<<<12500, 256>>>(h8);
    k_node<<<148, 512, SMEM_NODE>>>(hb0, Ws1, Wn1, b1, hb1, s1p, g1, be1, ab1, 1);

    // ---- layer 2 folded into readout (BN1 + final GEMV + softmax fused) ----
    k_colsum2<<<512, 256>>>(hb1, ab1, Ws2, Wn2, b2, out);
}